// round 6
// baseline (speedup 1.0000x reference)
#include <cuda_runtime.h>
#include <math_constants.h>

#define CC 192
#define KK 64
#define NBINS 2048
#define BIN_LO (-10.5f)
#define BIN_W  (21.0f / (float)NBINS)
#define BIN_INV ((float)NBINS / 21.0f)
// 2^23 + (-BIN_LO)*BIN_INV = 8388608 + 1024
#define BIN_MAGIC 8389632.0f
#define XCLAMP 10.49f
#define LIK_BOUND 1e-9f

// {y, lik} per (channel, code)
__device__ float2 g_tab[CC * KK];
// midpoints (63 real + 1 INF sentinel)
__device__ float g_mid[KK];
// per-bin: low byte = k0 (count with 2-bin slack), bit8 = dirty flag
__device__ unsigned short g_bin[NBINS];

__device__ __forceinline__ float softplusf(float x) {
    return fmaxf(x, 0.0f) + log1pf(expf(-fabsf(x)));
}

__device__ __forceinline__ int count_mids_below(const float* __restrict__ cb, float v) {
    int lo = 0, hi = KK - 1;   // lower_bound over 63 midpoints
    while (lo < hi) {
        int m = (lo + hi) >> 1;
        float mid = 0.5f * (cb[m] + cb[m + 1]);
        if (mid < v) lo = m + 1; else hi = m;
    }
    return lo;
}

// grid = 200 blocks x 128 threads.
// blocks [0,192): one channel each; tid<64 -> lower eval, tid>=64 -> upper eval.
// blocks [192,200): bin table (256 bins each) + midpoints (block 192).
__global__ void __launch_bounds__(128) build_lut_kernel(
    const float* __restrict__ cb,
    const float* __restrict__ m0, const float* __restrict__ m1,
    const float* __restrict__ m2, const float* __restrict__ m3,
    const float* __restrict__ m4,
    const float* __restrict__ b0, const float* __restrict__ b1,
    const float* __restrict__ b2, const float* __restrict__ b3,
    const float* __restrict__ b4,
    const float* __restrict__ f0, const float* __restrict__ f1,
    const float* __restrict__ f2, const float* __restrict__ f3)
{
    int tid = threadIdx.x;
    int blk = blockIdx.x;

    if (blk >= CC) {
        // ---- bin table + midpoints ----
        int bb = blk - CC;
        if (bb == 0 && tid < KK) {
            g_mid[tid] = (tid < KK - 1) ? 0.5f * (cb[tid] + cb[tid + 1]) : CUDART_INF_F;
        }
        #pragma unroll
        for (int r = 0; r < 2; r++) {
            int t = bb * 256 + r * 128 + tid;
            float wlo = BIN_LO + (float)(t - 2) * BIN_W;
            float whi = BIN_LO + (float)(t + 3) * BIN_W;
            int k0  = count_mids_below(cb, wlo);
            int khi = count_mids_below(cb, whi);
            unsigned short e = (unsigned short)k0;
            if (khi > k0) e |= 0x100;
            g_bin[t] = e;
        }
        return;
    }

    int c = blk;
    int s = tid >> 6;      // 0 = lower, 1 = upper
    int k = tid & 63;

    // per-thread param prep (independent transcendentals, good ILP)
    float w0[3], w4[3], bb0[3], bb1[3], bb2[3], bb3[3], bb4;
    float t0[3], t1[3], t2[3], t3[3];
    float w1[9], w2[9], w3[9];
    #pragma unroll
    for (int j = 0; j < 3; j++) {
        w0[j]  = softplusf(m0[c * 3 + j]);
        w4[j]  = softplusf(m4[c * 3 + j]);
        bb0[j] = b0[c * 3 + j];
        bb1[j] = b1[c * 3 + j];
        bb2[j] = b2[c * 3 + j];
        bb3[j] = b3[c * 3 + j];
        t0[j]  = tanhf(f0[c * 3 + j]);
        t1[j]  = tanhf(f1[c * 3 + j]);
        t2[j]  = tanhf(f2[c * 3 + j]);
        t3[j]  = tanhf(f3[c * 3 + j]);
    }
    #pragma unroll
    for (int j = 0; j < 9; j++) {
        w1[j] = softplusf(m1[c * 9 + j]);
        w2[j] = softplusf(m2[c * 9 + j]);
        w3[j] = softplusf(m3[c * 9 + j]);
    }
    bb4 = b4[c];

    float u = cb[k] + (s ? 0.5f : -0.5f);
    float h[3], nt[3];
    #pragma unroll
    for (int j = 0; j < 3; j++) {
        h[j] = w0[j] * u + bb0[j];
        h[j] += t0[j] * tanhf(h[j]);
    }
    #pragma unroll
    for (int j = 0; j < 3; j++) {
        nt[j] = w1[j*3+0]*h[0] + w1[j*3+1]*h[1] + w1[j*3+2]*h[2] + bb1[j];
        nt[j] += t1[j] * tanhf(nt[j]);
    }
    #pragma unroll
    for (int j = 0; j < 3; j++) h[j] = nt[j];
    #pragma unroll
    for (int j = 0; j < 3; j++) {
        nt[j] = w2[j*3+0]*h[0] + w2[j*3+1]*h[1] + w2[j*3+2]*h[2] + bb2[j];
        nt[j] += t2[j] * tanhf(nt[j]);
    }
    #pragma unroll
    for (int j = 0; j < 3; j++) h[j] = nt[j];
    #pragma unroll
    for (int j = 0; j < 3; j++) {
        nt[j] = w3[j*3+0]*h[0] + w3[j*3+1]*h[1] + w3[j*3+2]*h[2] + bb3[j];
        nt[j] += t3[j] * tanhf(nt[j]);
    }
    #pragma unroll
    for (int j = 0; j < 3; j++) h[j] = nt[j];
    float out = w4[0]*h[0] + w4[1]*h[1] + w4[2]*h[2] + bb4;

    __shared__ float souts[2][KK];
    souts[s][k] = out;
    __syncthreads();

    if (tid < KK) {
        float lo = souts[0][tid], up = souts[1][tid];
        float ssum = lo + up;
        float sg = (ssum > 0.0f) ? -1.0f : ((ssum < 0.0f) ? 1.0f : 0.0f);
        float su = 1.0f / (1.0f + expf(-sg * up));
        float sl = 1.0f / (1.0f + expf(-sg * lo));
        float lik = fmaxf(fabsf(su - sl), LIK_BOUND);
        g_tab[c * KK + tid] = make_float2(cb[tid], lik);
    }
}

// Each block = 256 threads x 4 float4 = 4096 elements = exactly one (n,c) plane.
__global__ void __launch_bounds__(256) quant_lik_kernel(
    const float4* __restrict__ x4,
    float4* __restrict__ y4,
    float4* __restrict__ l4)
{
    __shared__ float2 stab[KK];
    __shared__ float  smid[KK];
    __shared__ unsigned short sbin[NBINS];

    int tid = threadIdx.x;
    int c = blockIdx.x % CC;

    if (tid < KK) {
        stab[tid] = g_tab[c * KK + tid];
        smid[tid] = g_mid[tid];
    }
    // 2048 u16 = 4KB: one int4 per thread
    ((int4*)sbin)[tid] = ((const int4*)g_bin)[tid];
    __syncthreads();

    long base = (long)blockIdx.x * 1024 + tid;  // float4 units; stride 256

    // Phase 1: all loads in flight (MLP=4)
    float4 xv[4];
    #pragma unroll
    for (int v = 0; v < 4; v++) xv[v] = __ldcs(&x4[base + v * 256]);

    const float* xs = (const float*)xv;

    // Phase 2: 16 independent bin lookups (LDS pipelined back-to-back)
    int ee[16];
    #pragma unroll
    for (int t = 0; t < 16; t++) {
        float xx = fminf(fmaxf(xs[t], -XCLAMP), XCLAMP);
        int bin = __float_as_int(fmaf(xx, BIN_INV, BIN_MAGIC)) & 0x7FF;
        ee[t] = sbin[bin];
    }

    // Phase 3: resolve dirty bins (rare; ~15% of elements, branch-guarded)
    #pragma unroll
    for (int t = 0; t < 16; t++) {
        int e = ee[t];
        int k = e & 0xFF;
        if (e & 0x100) {
            float xx = xs[t];
            k += (smid[k] < xx);
            k += (smid[k] < xx);
            k += (smid[k] < xx);
            while (smid[k] < xx) k++;   // smid[63] = +INF bounds
        }
        ee[t] = k;
    }

    // Phase 4: gather + streaming stores
    #pragma unroll
    for (int v = 0; v < 4; v++) {
        float2 a = stab[ee[v*4+0]];
        float2 b = stab[ee[v*4+1]];
        float2 cc2 = stab[ee[v*4+2]];
        float2 d = stab[ee[v*4+3]];
        long i = base + v * 256;
        __stcs(&y4[i], make_float4(a.x, b.x, cc2.x, d.x));
        __stcs(&l4[i], make_float4(a.y, b.y, cc2.y, d.y));
    }
}

extern "C" void kernel_launch(void* const* d_in, const int* in_sizes, int n_in,
                              void* d_out, int out_size)
{
    // metadata order: x, codebook, m0, b0, f0, m1, b1, f1, m2, b2, f2, m3, b3, f3, m4, b4
    const float* x  = (const float*)d_in[0];
    const float* cb = (const float*)d_in[1];
    const float* m0 = (const float*)d_in[2];
    const float* b0 = (const float*)d_in[3];
    const float* f0 = (const float*)d_in[4];
    const float* m1 = (const float*)d_in[5];
    const float* b1 = (const float*)d_in[6];
    const float* f1 = (const float*)d_in[7];
    const float* m2 = (const float*)d_in[8];
    const float* b2 = (const float*)d_in[9];
    const float* f2 = (const float*)d_in[10];
    const float* m3 = (const float*)d_in[11];
    const float* b3 = (const float*)d_in[12];
    const float* f3 = (const float*)d_in[13];
    const float* m4 = (const float*)d_in[14];
    const float* b4 = (const float*)d_in[15];

    long total = (long)in_sizes[0];        // 16*192*64*64 = 12582912
    int nblocks = (int)(total / 4096);     // one (n,c) plane per block

    float* yhat = (float*)d_out;
    float* lik  = (float*)d_out + total;

    build_lut_kernel<<<CC + NBINS / 256, 128>>>(
        cb, m0, m1, m2, m3, m4, b0, b1, b2, b3, b4, f0, f1, f2, f3);

    quant_lik_kernel<<<nblocks, 256>>>(
        (const float4*)x, (float4*)yhat, (float4*)lik);
}